// round 5
// baseline (speedup 1.0000x reference)
#include <cuda_runtime.h>

#define B    100
#define DIN  2048
#define DH   1024
#define DOUT 1000

__device__ float d_hacc[B * DH];   // gemm1 + b1-sum accumulator (pre-scaled 1/DIN)
__device__ int   d_cnt[16];        // last-reader counters for d_hacc k-slices

#define G1_BLOCKS 256              // gemm1: 16 ntiles x 16 ksplits (kc=128)
#define OZ_BLOCKS 98               // out-zero: 98 * 256 * 4 >= 100000 floats
#define R1_BLOCKS 1600             // reduce_b1: 100 batches x 16 chunks (128 rows)
#define G2_BLOCKS 256              // gemm2: 16 ntiles x 16 ksplits (kc=64)
#define R2_BLOCKS 1600             // reduce_b2: 100 batches x 16 chunks (64 rows)

// ---------------------------------------------------------------------------
// SIMT GEMM tile: all 100 M-rows x 64 N-cols, K range [k0, k0+kc).
// 256 threads: thread owns 7 m x 4 n. Accumulates scale*r into acc atomically.
// relu_in: max(v,0) applied to A on load.
// zslice >= 0: last-reader protocol — 16 blocks read A k-slice `zslice`;
// the 16th re-zeros d_hacc[:, zslice*64 .. +63] and resets the counter,
// restoring the d_hacc==0 invariant for the next graph replay.
__device__ __forceinline__ void gemm_block(const float* __restrict__ A,
                                           const float* __restrict__ Wm,
                                           float* __restrict__ acc,
                                           int K, int N, int ldacc,
                                           int k0, int kc, int n0,
                                           float scale, bool relu_in,
                                           int zslice) {
    // Explicit 16B alignment: ws is read through a float4* cast below, and
    // shared-layout ordering must not be relied on for that (R4 bug).
    __shared__ __align__(16) float xs[112][33]; // pad 33: strips hit distinct banks
    __shared__ __align__(16) float ws[32][64];
    __shared__ int do_zero;

    const int tid = threadIdx.x;
    const int nl4 = tid & 15;        // 16 lanes * 4 cols = 64
    const int m0  = (tid >> 4) * 7;  // 16 strips * 7 = 112 >= 100

    float r[7][4];
#pragma unroll
    for (int i = 0; i < 7; ++i)
#pragma unroll
        for (int j = 0; j < 4; ++j) r[i][j] = 0.f;

    for (int kb = k0; kb < k0 + kc; kb += 32) {
        for (int idx = tid; idx < 112 * 32; idx += 256) {
            int m = idx >> 5, kk = idx & 31;
            float v = (m < B) ? A[(long long)m * K + kb + kk] : 0.f;
            if (relu_in) v = fmaxf(v, 0.f);
            xs[m][kk] = v;
        }
        for (int idx = tid; idx < 32 * 64; idx += 256) {
            int kk = idx >> 6, nn = idx & 63;
            int nc = n0 + nn;
            ws[kk][nn] = (nc < N) ? Wm[(long long)(kb + kk) * N + nc] : 0.f;
        }
        __syncthreads();
#pragma unroll
        for (int kk = 0; kk < 32; ++kk) {
            float4 wv = *(const float4*)&ws[kk][nl4 * 4];
#pragma unroll
            for (int mi = 0; mi < 7; ++mi) {
                float xv = xs[m0 + mi][kk];
                r[mi][0] += xv * wv.x; r[mi][1] += xv * wv.y;
                r[mi][2] += xv * wv.z; r[mi][3] += xv * wv.w;
            }
        }
        __syncthreads();
    }

#pragma unroll
    for (int mi = 0; mi < 7; ++mi) {
        int m = m0 + mi;
        if (m < B) {
            int n = n0 + nl4 * 4;
#pragma unroll
            for (int j = 0; j < 4; ++j)
                if (n + j < N)
                    atomicAdd(&acc[(long long)m * ldacc + n + j], r[mi][j] * scale);
        }
    }

    // Last-reader re-zero of the A k-slice (all this block's A reads are done).
    if (zslice >= 0) {
        if (tid == 0) {
            int old = atomicAdd(&d_cnt[zslice], 1);
            do_zero = (old == 15);
            if (old == 15) d_cnt[zslice] = 0;   // self-reset for next replay
        }
        __syncthreads();
        if (do_zero) {
            int c0 = zslice * 64;
            for (int idx = tid; idx < B * 64; idx += 256)
                d_hacc[(idx >> 6) * DH + c0 + (idx & 63)] = 0.f;
        }
    }
}

// ---------------------------------------------------------------------------
// Column-sum of `rows` rows of a [rows_total x width] slab into acc row b,
// scaled. Coalesced float4 loads; up to width/4 threads active.
__device__ __forceinline__ void reduce_block(const float* __restrict__ src,
                                             float* __restrict__ acc,
                                             int b, int chunk, int rows,
                                             int rows_total, int width,
                                             float scale) {
    const int wq = width >> 2;
    const int j4 = threadIdx.x;
    if (j4 >= wq) return;
    const long long base = (long long)b * rows_total * width +
                           (long long)chunk * rows * width + j4 * 4;
    const float4* p = (const float4*)(src + base);
    float4 s = make_float4(0.f, 0.f, 0.f, 0.f);
#pragma unroll 16
    for (int i = 0; i < rows; ++i) {
        float4 v = p[(long long)i * wq];
        s.x += v.x; s.y += v.y; s.z += v.z; s.w += v.w;
    }
    float* o = acc + (long long)b * width + j4 * 4;
    atomicAdd(o + 0, s.x * scale); atomicAdd(o + 1, s.y * scale);
    atomicAdd(o + 2, s.z * scale); atomicAdd(o + 3, s.w * scale);
}

// ---------------------------------------------------------------------------
// mega1: gemm1 (256) + out-zero (98) + reduce_b1 (1600), into d_hacc / out.
__global__ void __launch_bounds__(256, 6)
mega1_kernel(const float* __restrict__ x,
             const float* __restrict__ W1,
             const float* __restrict__ b1,
             float* __restrict__ out) {
    int bid = blockIdx.x;
    if (bid < G1_BLOCKS) {
        int nt = bid & 15, ks = bid >> 4;
        gemm_block(x, W1, d_hacc, DIN, DH, DH, ks * 128, 128, nt * 64,
                   1.0f / DIN, false, -1);
    } else if (bid < G1_BLOCKS + OZ_BLOCKS) {
        int i = ((bid - G1_BLOCKS) * 256 + threadIdx.x) * 4;
        if (i < B * DOUT) {
            out[i] = 0.f;
            if (i + 1 < B * DOUT) out[i + 1] = 0.f;
            if (i + 2 < B * DOUT) out[i + 2] = 0.f;
            if (i + 3 < B * DOUT) out[i + 3] = 0.f;
        }
    } else {
        int r = bid - (G1_BLOCKS + OZ_BLOCKS);
        reduce_block(b1, d_hacc, r >> 4, r & 15, 128, DIN, DH, 1.0f / DIN);
    }
}

// mega2: gemm2 (256, relu on A-load, last-reader re-zero of d_hacc)
//        + reduce_b2 (1600), both accumulating into out.
__global__ void __launch_bounds__(256, 6)
mega2_kernel(const float* __restrict__ W2,
             const float* __restrict__ b2,
             float* __restrict__ out) {
    int bid = blockIdx.x;
    if (bid < G2_BLOCKS) {
        int nt = bid & 15, ks = bid >> 4;
        gemm_block(d_hacc, W2, out, DH, DOUT, DOUT, ks * 64, 64, nt * 64,
                   1.0f / DH, true, ks);
    } else {
        int r = bid - G2_BLOCKS;
        reduce_block(b2, out, r >> 4, r & 15, 64, DH, DOUT, 1.0f / DH);
    }
}

// ---------------------------------------------------------------------------
extern "C" void kernel_launch(void* const* d_in, const int* in_sizes, int n_in,
                              void* d_out, int out_size) {
    const float* x  = (const float*)d_in[0];
    const float* W1 = (const float*)d_in[1];
    const float* b1 = (const float*)d_in[2];
    const float* W2 = (const float*)d_in[3];
    const float* b2 = (const float*)d_in[4];
    float* out = (float*)d_out;

    mega1_kernel<<<G1_BLOCKS + OZ_BLOCKS + R1_BLOCKS, 256>>>(x, W1, b1, out);
    mega2_kernel<<<G2_BLOCKS + R2_BLOCKS, 256>>>(W2, b2, out);
}